// round 11
// baseline (speedup 1.0000x reference)
#include <cuda_runtime.h>

// SparseBiasDiagUnfolder — FINAL (= R9, best measured 6.496us).
// One wave: 146 blocks x 896 threads (28 warps/CTA), 2 window-rows per warp,
// div-free and fully 32-bit index math.
//
//   adj: (B=2, N=2048, N=2048, F=16) fp32; starts 0,4,...,2040 (511);
//   out (B, 511, 56*16).
//
// Max float4 index into adj = 2*2048*2048*4 = 2^25  -> fits in 32-bit.
// Warp w covers rows [2w, 2w+2), both share bs = w>>2 = b*511+s (bs<1022,
// so b = bs>=511: no division). Each row is a 512B contiguous run: lane l
// loads float4 base+l -> 2 independent fully-coalesced LDG.128 batched up
// front (MLP_p1=2, 56 loads in flight per SM). Stores: 28 active lanes/row
// write a contiguous 448B run (diagonal chunk dropped,
// pos = ii*7 + jj - (jj>ii)).
//
// Optimization history (wall us): naive gather 6.88 -> one-wave grid 6.56
// -> div-free math 6.62 -> 28 warps/CTA + 32-bit addressing 6.50.
// All SOL pipes <10% busy; residue is launch/replay floor.

namespace {
constexpr int N        = 2048;
constexpr int NSTARTS  = 511;
constexpr int WARPS_PER_BLOCK = 28;
constexpr int THREADS  = WARPS_PER_BLOCK * 32;   // 896
constexpr int BLOCKS   = 146;                    // 4088 warps = 8176 rows / 2
}

__global__ void __launch_bounds__(THREADS)
sparse_diag_unfold_kernel(const float4* __restrict__ adj, float4* __restrict__ out)
{
    const unsigned gt   = blockIdx.x * THREADS + threadIdx.x;
    const unsigned w    = gt >> 5;                 // 0..4087
    const unsigned lane = gt & 31;

    const unsigned bs      = w >> 2;               // b*511 + s, < 1022
    const unsigned ii_base = (w & 3) * 2;          // 0,2,4,6

    const unsigned b = (bs >= NSTARTS);            // no division
    const unsigned s = bs - b * NSTARTS;

    // 32-bit float4 base index of row (bs, ii_base):
    //   b*N*N*4 + s*(N+1)*16 + ii_base*N*4 + lane   (max ~2^25)
    const unsigned base0 = b * (N * N * 4u)
                         + s * ((N + 1) * 16u)
                         + ii_base * (N * 4u)
                         + lane;

    const unsigned jj = lane >> 2;
    const unsigned v  = lane & 3;

    // 2 independent coalesced 512B loads, batched (MLP_p1 = 2).
    float4 vals[2];
    #pragma unroll
    for (int k = 0; k < 2; k++)
        vals[k] = adj[base0 + (unsigned)k * (N * 4u)];

    const unsigned out_base = bs * (56u * 4u);
    #pragma unroll
    for (int k = 0; k < 2; k++) {
        const unsigned ii = ii_base + k;
        if (jj != ii) {
            const unsigned pos = ii * 7u + jj - (jj > ii);   // 0..55
            out[out_base + pos * 4u + v] = vals[k];
        }
    }
}

extern "C" void kernel_launch(void* const* d_in, const int* in_sizes, int n_in,
                              void* d_out, int out_size)
{
    const float4* adj = (const float4*)d_in[0];
    float4* out = (float4*)d_out;
    sparse_diag_unfold_kernel<<<BLOCKS, THREADS>>>(adj, out);
}

// round 12
// speedup vs baseline: 1.0048x; 1.0048x over previous
#include <cuda_runtime.h>

// SparseBiasDiagUnfolder — output-centric: one float4 per thread, store
// index == global thread id (perfect coalescing, all 32 lanes active,
// zero predication). Loads: <=2 contiguous segments per warp.
//
//   adj: (B=2, N=2048, N=2048, F=16) fp32; starts 0,4,...,2040 (511);
//   out (B, 511, 56*16)  = 228,928 float4s = 7154 warps of 32.
//
// Warp w covers out float4s [32w, 32w+32):
//   bs = w / 7   (magic multiply: w*149797 >> 20, exact for w < 349525)
//   u  = w - 7*bs            (which 8-position chunk of the 56)
//   pos = 8u + (lane>>2), v = lane&3
//   local = pos + 1 + (pos>>3) = pos + 1 + u   (pos>>3 == u within chunk)
//   ii = local>>3, jj = local&7
//   b = (bs >= 511), s = bs - 511*b            (no division)
// Load float4 index = b*N*N*4 + s*(N+1)*16 + (ii*N + jj)*4 + v  (32-bit).

namespace {
constexpr int N        = 2048;
constexpr int NSTARTS  = 511;
constexpr int THREADS  = 448;        // 14 warps
constexpr int BLOCKS   = 511;        // 7154 warps total (exact)
}

__global__ void __launch_bounds__(THREADS)
sparse_diag_unfold_kernel(const float4* __restrict__ adj, float4* __restrict__ out)
{
    const unsigned gt   = blockIdx.x * THREADS + threadIdx.x;  // == out index
    const unsigned w    = gt >> 5;                 // 0..7153
    const unsigned lane = gt & 31;

    const unsigned bs = (w * 149797u) >> 20;       // w / 7 (exact here)
    const unsigned u  = w - bs * 7u;               // 0..6

    const unsigned pos   = u * 8u + (lane >> 2);   // 0..55
    const unsigned v     = lane & 3u;
    const unsigned local = pos + 1u + u;           // skip diagonal
    const unsigned ii    = local >> 3;
    const unsigned jj    = local & 7u;

    const unsigned b = (bs >= NSTARTS);
    const unsigned s = bs - b * NSTARTS;

    const unsigned src = b * (N * N * 4u)
                       + s * ((N + 1) * 16u)
                       + (ii * N + jj) * 4u
                       + v;

    out[gt] = adj[src];    // store: fully contiguous, all lanes active
}

extern "C" void kernel_launch(void* const* d_in, const int* in_sizes, int n_in,
                              void* d_out, int out_size)
{
    const float4* adj = (const float4*)d_in[0];
    float4* out = (float4*)d_out;
    sparse_diag_unfold_kernel<<<BLOCKS, THREADS>>>(adj, out);
}